// round 16
// baseline (speedup 1.0000x reference)
#include <cuda_runtime.h>
#include <cuda_bf16.h>
#include <math.h>
#include <stdint.h>

#define N_  32
#define D_  512
#define P_  4096
#define K_  64
#define EPSF 1e-12f

// ---------------- scratch (device globals) ----------------------------------
__device__ __nv_bfloat16 g_ah[(size_t)N_ * K_ * P_];    // a*invn bf16 (16 MB)
__device__ __nv_bfloat16 g_xh[(size_t)N_ * D_ * P_];    // x bf16 (128 MB)
__device__ __nv_bfloat16 g_wh[K_ * D_];                 // W bf16 (64 KB)
__device__ float g_asum[N_ * K_];
__device__ float g_vlad[(size_t)N_ * K_ * D_];          // 4 MB
__device__ float g_gnorm2[N_];

// ---------------- helpers ----------------------------------------------------
__device__ __forceinline__ uint32_t smem_u32(const void* p) {
    uint32_t a;
    asm("{ .reg .u64 t; cvta.to.shared.u64 t, %1; cvt.u32.u64 %0, t; }" : "=r"(a) : "l"(p));
    return a;
}
__device__ __forceinline__ void mma_bf16(float* c, const uint32_t* a, const uint32_t* b) {
    asm volatile(
        "mma.sync.aligned.m16n8k16.row.col.f32.bf16.bf16.f32 "
        "{%0,%1,%2,%3}, {%4,%5,%6,%7}, {%8,%9}, {%0,%1,%2,%3};"
        : "+f"(c[0]), "+f"(c[1]), "+f"(c[2]), "+f"(c[3])
        : "r"(a[0]), "r"(a[1]), "r"(a[2]), "r"(a[3]), "r"(b[0]), "r"(b[1]));
}
__device__ __forceinline__ void ldsm4(uint32_t* r, const void* p) {
    uint32_t a = smem_u32(p);
    asm volatile("ldmatrix.sync.aligned.m8n8.x4.shared.b16 {%0,%1,%2,%3}, [%4];"
        : "=r"(r[0]), "=r"(r[1]), "=r"(r[2]), "=r"(r[3]) : "r"(a));
}
__device__ __forceinline__ uint32_t pk2(__nv_bfloat16 a, __nv_bfloat16 b) {
    return (uint32_t)__bfloat16_as_ushort(a) | ((uint32_t)__bfloat16_as_ushort(b) << 16);
}
__device__ __forceinline__ void cp16(void* dst_smem, const void* src) {
    asm volatile("cp.async.cg.shared.global [%0], [%1], 16;"
                 :: "r"(smem_u32(dst_smem)), "l"(src) : "memory");
}
#define CP_COMMIT() asm volatile("cp.async.commit_group;" ::: "memory")
#define CP_WAIT0()  asm volatile("cp.async.wait_group 0;" ::: "memory")

// ---------------- k0: zero scratch + convert W to bf16 ------------------------
__global__ void k0_init(const float* __restrict__ wgt) {
    int i = blockIdx.x * 256 + threadIdx.x;
    if (i < N_ * K_) g_asum[i] = 0.f;
    if (i < N_)      g_gnorm2[i] = 0.f;
    if (i < K_ * D_) g_wh[i] = __float2bfloat16_rn(wgt[i]);
    for (int e = i; e < N_ * K_ * D_; e += gridDim.x * 256) g_vlad[e] = 0.f;
}

// ---------------- k2: fused norm + logits GEMM + softmax + a_eff + x_bf16 ----
// block = (n, 128 pixels), 128 threads (4 warps). R14 winner + x_bf16 export.
#define ST2 40
#define WPART (64 * ST2)
#define TPART (128 * ST2)
#define BUF2_B ((WPART + TPART) * 2)            // 15360 bytes per buffer
#define LS_B (64 * 132 * 4)                     // 33792
#define K2_SMEM (LS_B + 512)                    // Ls unioned over both buffers

__global__ __launch_bounds__(128) void k2_mma(const float* __restrict__ x) {
    extern __shared__ char sm2[];
    float* Ls = (float*)sm2;                    // [64][132] — UNION with staging
    float* sInv = (float*)(sm2 + LS_B);         // [128]

    const int n  = blockIdx.y;
    const int p0 = blockIdx.x * 128;
    const int tid = threadIdx.x;
    const int w = tid >> 5, lane = tid & 31;
    const int g = lane >> 2, tc = lane & 3;

    const int a_row = (lane & 15);
    const int a_col = (lane >> 4) << 3;
    const int b_row = ((lane >> 4) << 3) + (lane & 7);
    const int b_col = ((lane >> 3) & 1) << 3;

    float acc[4][4][4];
    #pragma unroll
    for (int i = 0; i < 4; i++)
        #pragma unroll
        for (int j = 0; j < 4; j++)
            #pragma unroll
            for (int q = 0; q < 4; q++) acc[i][j][q] = 0.f;

    const float* xb = x + (size_t)n * D_ * P_ + p0 + tid;
    __nv_bfloat16* xhp = g_xh + (size_t)n * D_ * P_ + p0 + tid;
    float ss = 0.f;

    const int wrow = tid >> 1;
    const int wseg = (tid & 1) * 16;

    float xr[32];

    // ---- prologue: stage chunk 0 into buffer 0 (+ export bf16 x) ----
    {
        char* buf = sm2;
        __nv_bfloat16* Wh = (__nv_bfloat16*)buf;
        __nv_bfloat16* Th = Wh + WPART;
        cp16(Wh + wrow * ST2 + wseg,     g_wh + wrow * D_ + wseg);
        cp16(Wh + wrow * ST2 + wseg + 8, g_wh + wrow * D_ + wseg + 8);
        CP_COMMIT();
        #pragma unroll
        for (int dd = 0; dd < 32; dd++) xr[dd] = xb[(size_t)dd * P_];
        #pragma unroll
        for (int dd = 0; dd < 32; dd += 4) {
            float4 v = {xr[dd], xr[dd + 1], xr[dd + 2], xr[dd + 3]};
            ss += v.x * v.x + v.y * v.y + v.z * v.z + v.w * v.w;
            __nv_bfloat16 b0 = __float2bfloat16_rn(v.x), b1 = __float2bfloat16_rn(v.y);
            __nv_bfloat16 b2 = __float2bfloat16_rn(v.z), b3 = __float2bfloat16_rn(v.w);
            uint2 h = { pk2(b0, b1), pk2(b2, b3) };
            *(uint2*)(Th + tid * ST2 + dd) = h;
            xhp[(size_t)(dd + 0) * P_] = b0;
            xhp[(size_t)(dd + 1) * P_] = b1;
            xhp[(size_t)(dd + 2) * P_] = b2;
            xhp[(size_t)(dd + 3) * P_] = b3;
        }
        CP_WAIT0();
        __syncthreads();
    }

    for (int dc = 0; dc < 16; dc++) {
        const int b = dc & 1;
        char* buf = sm2 + b * BUF2_B;
        const __nv_bfloat16* Wh = (const __nv_bfloat16*)buf;
        const __nv_bfloat16* Th = Wh + WPART;

        char* nbuf = sm2 + (b ^ 1) * BUF2_B;
        __nv_bfloat16* nWh = (__nv_bfloat16*)nbuf;
        __nv_bfloat16* nTh = nWh + WPART;

        const bool more = (dc + 1 < 16);
        const int nd0 = (dc + 1) * 32;
        if (more) {
            cp16(nWh + wrow * ST2 + wseg,     g_wh + wrow * D_ + nd0 + wseg);
            cp16(nWh + wrow * ST2 + wseg + 8, g_wh + wrow * D_ + nd0 + wseg + 8);
            CP_COMMIT();
            #pragma unroll
            for (int dd = 0; dd < 32; dd++) xr[dd] = xb[(size_t)(nd0 + dd) * P_];
        }

        // ---- MMA on current buffer (single bf16 pass, ldmatrix feeds) ----
        const __nv_bfloat16* Arow = Wh + a_row * ST2 + a_col;
        const __nv_bfloat16* B01  = Th + (w * 32 + b_row) * ST2 + b_col;
        const __nv_bfloat16* B23  = B01 + 16 * ST2;
        #pragma unroll
        for (int ks = 0; ks < 2; ks++) {
            const int kb = ks * 16;
            uint32_t Bt[8];
            ldsm4(Bt,     B01 + kb);
            ldsm4(Bt + 4, B23 + kb);
            #pragma unroll
            for (int mt = 0; mt < 4; mt++) {
                uint32_t Ah[4];
                ldsm4(Ah, Arow + mt * 16 * ST2 + kb);
                #pragma unroll
                for (int t = 0; t < 4; t++)
                    mma_bf16(acc[mt][t], Ah, Bt + t * 2);
            }
        }

        if (more) {
            #pragma unroll
            for (int dd = 0; dd < 32; dd += 4) {
                float4 v = {xr[dd], xr[dd + 1], xr[dd + 2], xr[dd + 3]};
                ss += v.x * v.x + v.y * v.y + v.z * v.z + v.w * v.w;
                __nv_bfloat16 b0 = __float2bfloat16_rn(v.x), b1 = __float2bfloat16_rn(v.y);
                __nv_bfloat16 b2 = __float2bfloat16_rn(v.z), b3 = __float2bfloat16_rn(v.w);
                uint2 h = { pk2(b0, b1), pk2(b2, b3) };
                *(uint2*)(nTh + tid * ST2 + dd) = h;
                xhp[(size_t)(nd0 + dd + 0) * P_] = b0;
                xhp[(size_t)(nd0 + dd + 1) * P_] = b1;
                xhp[(size_t)(nd0 + dd + 2) * P_] = b2;
                xhp[(size_t)(nd0 + dd + 3) * P_] = b3;
            }
            CP_WAIT0();
        }
        __syncthreads();
    }

    const float invnv = 1.0f / fmaxf(sqrtf(ss), EPSF);
    sInv[tid] = invnv;
    __syncthreads();

    // epilogue: scale by invn, stage logits into Ls (staging buffers dead now)
    #pragma unroll
    for (int mt = 0; mt < 4; mt++)
        #pragma unroll
        for (int t = 0; t < 4; t++) {
            int col = w * 32 + t * 8 + tc * 2;
            int row = mt * 16 + g;
            Ls[row * 132 + col]           = acc[mt][t][0] * sInv[col];
            Ls[row * 132 + col + 1]       = acc[mt][t][1] * sInv[col + 1];
            Ls[(row + 8) * 132 + col]     = acc[mt][t][2] * sInv[col];
            Ls[(row + 8) * 132 + col + 1] = acc[mt][t][3] * sInv[col + 1];
        }
    __syncthreads();

    // softmax over clusters; one thread per pixel column
    {
        float m = -1e30f;
        for (int k = 0; k < 64; k++) m = fmaxf(m, Ls[k * 132 + tid]);
        float s = 0.f;
        for (int k = 0; k < 64; k++) {
            float e = expf(Ls[k * 132 + tid] - m);
            Ls[k * 132 + tid] = e;
            s += e;
        }
        float inv = 1.0f / s;
        for (int k = 0; k < 64; k++) Ls[k * 132 + tid] *= inv;
    }
    __syncthreads();

    // write a_eff = a * invn as bf16
    {
        __nv_bfloat16* ah = g_ah + (size_t)n * K_ * P_ + p0 + tid;
        for (int k = 0; k < 64; k++) {
            float ae = Ls[k * 132 + tid] * invnv;
            ah[(size_t)k * P_] = __float2bfloat16_rn(ae);
        }
    }
    if (tid < 64) {
        float s = 0.f;
        for (int p = 0; p < 128; p++) s += Ls[tid * 132 + p];
        atomicAdd(&g_asum[n * K_ + tid], s);
    }
}

// ---------------- k3: vlad GEMM, all-cp.async, single-pass bf16 --------------
#define PC3 64
#define ST3 72
#define XPART (128 * ST3)
#define APART (64 * ST3)
#define BUF_B ((XPART + APART) * 2)           // 27648 bytes per buffer
#define K3_SMEM (2 * BUF_B)                    // 55296 bytes
#define NCH3 (2048 / PC3)                      // 32 chunks per half

__global__ __launch_bounds__(512, 2) void k3_mma() {
    extern __shared__ char sm3[];

    const int n    = blockIdx.z;
    const int d0   = blockIdx.x * 128;
    const int pho  = blockIdx.y * 2048;
    const int tid  = threadIdx.x;
    const int w = tid >> 5, lane = tid & 31;
    const int g = lane >> 2, tc = lane & 3;
    const int mt = w >> 1;
    const int nh = (w & 1) * 32;

    const int a_rowoff = (mt * 16 + (lane & 15)) * ST3 + ((lane >> 4) << 3);
    const int b_rowoff = (nh + ((lane >> 4) << 3) + (lane & 7)) * ST3 + (((lane >> 3) & 1) << 3);

    const __nv_bfloat16* gxh = g_xh + ((size_t)n * D_ + d0) * P_ + pho;
    const __nv_bfloat16* gah = g_ah + (size_t)n * K_ * P_ + pho;

    float acc[4][4];
    #pragma unroll
    for (int t = 0; t < 4; t++)
        #pragma unroll
        for (int q = 0; q < 4; q++) acc[t][q] = 0.f;

    const int arow = tid >> 3;          // A: 64 rows x 8 segs
    const int aseg = tid & 7;
    const int xrow0 = tid >> 2;         // X: 128 rows x 8 segs, 2 per thread
    const int xseg0 = (tid & 3) * 2;

    {   // prologue: stage chunk 0
        char* buf = sm3;
        __nv_bfloat16* Xh = (__nv_bfloat16*)buf;
        __nv_bfloat16* Ahs = Xh + XPART;
        cp16(Xh + xrow0 * ST3 + xseg0 * 8,       gxh + (size_t)xrow0 * P_ + xseg0 * 8);
        cp16(Xh + xrow0 * ST3 + (xseg0 + 1) * 8, gxh + (size_t)xrow0 * P_ + (xseg0 + 1) * 8);
        cp16(Ahs + arow * ST3 + aseg * 8,        gah + (size_t)arow * P_ + aseg * 8);
        CP_COMMIT();
        CP_WAIT0();
        __syncthreads();
    }

    for (int pc = 0; pc < NCH3; pc++) {
        const int b = pc & 1;
        char* buf = sm3 + b * BUF_B;
        const __nv_bfloat16* Xh = (const __nv_bfloat16*)buf;
        const __nv_bfloat16* Ahs = Xh + XPART;

        char* nbuf = sm3 + (b ^ 1) * BUF_B;
        __nv_bfloat16* nXh = (__nv_bfloat16*)nbuf;
        __nv_bfloat16* nAh = nXh + XPART;

        const bool more = (pc + 1 < NCH3);
        if (more) {
            const int pb = (pc + 1) * PC3;
            cp16(nXh + xrow0 * ST3 + xseg0 * 8,       gxh + (size_t)xrow0 * P_ + pb + xseg0 * 8);
            cp16(nXh + xrow0 * ST3 + (xseg0 + 1) * 8, gxh + (size_t)xrow0 * P_ + pb + (xseg0 + 1) * 8);
            cp16(nAh + arow * ST3 + aseg * 8,         gah + (size_t)arow * P_ + pb + aseg * 8);
            CP_COMMIT();
        }

        // ---- MMA on current buffer ----
        #pragma unroll
        for (int ks = 0; ks < 4; ks++) {
            const int kb = ks * 16;
            uint32_t Bh[8];
            ldsm4(Bh,     Ahs + b_rowoff + kb);
            ldsm4(Bh + 4, Ahs + b_rowoff + 16 * ST3 + kb);
            uint32_t Ah[4];
            ldsm4(Ah, Xh + a_rowoff + kb);
            #pragma unroll
            for (int t = 0; t < 4; t++)
                mma_bf16(acc[t], Ah, Bh + t * 2);
        }

        if (more) CP_WAIT0();
        __syncthreads();
    }

    // epilogue: atomic-accumulate into g_vlad (2-way contention across p-halves)
    float* vb = g_vlad + (size_t)n * K_ * D_ + d0;
    const int r = mt * 16 + g;
    #pragma unroll
    for (int t = 0; t < 4; t++) {
        int kc = nh + t * 8 + tc * 2;
        atomicAdd(&vb[(size_t)kc * D_ + r],           acc[t][0]);
        atomicAdd(&vb[(size_t)(kc + 1) * D_ + r],     acc[t][1]);
        atomicAdd(&vb[(size_t)kc * D_ + r + 8],       acc[t][2]);
        atomicAdd(&vb[(size_t)(kc + 1) * D_ + r + 8], acc[t][3]);
    }
}

// ---------------- k4a: centroid subtraction + intra-normalize -----------------
__global__ __launch_bounds__(128) void k4a_finalize(
        const float* __restrict__ cent, float* __restrict__ out) {
    const int k = blockIdx.x, n = blockIdx.y;
    const int tid = threadIdx.x;
    const float asum = g_asum[n * K_ + k];
    const float* vl = g_vlad + ((size_t)n * K_ + k) * D_;
    const float* ck = cent + (size_t)k * D_;

    float t[4];
    float s2 = 0.f;
    #pragma unroll
    for (int r = 0; r < 4; r++) {
        int d = r * 128 + tid;
        t[r] = vl[d] - asum * ck[d];
        s2 += t[r] * t[r];
    }
    #pragma unroll
    for (int o = 16; o > 0; o >>= 1) s2 += __shfl_xor_sync(0xffffffffu, s2, o);
    __shared__ float red[4];
    if ((tid & 31) == 0) red[tid >> 5] = s2;
    __syncthreads();
    float total = red[0] + red[1] + red[2] + red[3];
    float inv = 1.0f / fmaxf(sqrtf(total), EPSF);

    float* o = out + ((size_t)n * K_ + k) * D_;
    #pragma unroll
    for (int r = 0; r < 4; r++) o[r * 128 + tid] = t[r] * inv;
    if (tid == 0) atomicAdd(&g_gnorm2[n], total * inv * inv);
}

// ---------------- k4b: global L2 scale -----------------------------------------
__global__ void k4b_global(float* __restrict__ out) {
    int i = blockIdx.x * 256 + threadIdx.x;
    int n = i >> 15;
    float inv = 1.0f / fmaxf(sqrtf(g_gnorm2[n]), EPSF);
    out[i] *= inv;
}

// ---------------- launch --------------------------------------------------------
extern "C" void kernel_launch(void* const* d_in, const int* in_sizes, int n_in,
                              void* d_out, int out_size) {
    const float* x = (const float*)d_in[0];
    const float* w = (const float*)d_in[1];
    const float* c = (const float*)d_in[2];
    float* out = (float*)d_out;

    static bool attr_done = false;
    if (!attr_done) {
        cudaFuncSetAttribute(k2_mma, cudaFuncAttributeMaxDynamicSharedMemorySize, K2_SMEM);
        cudaFuncSetAttribute(k3_mma, cudaFuncAttributeMaxDynamicSharedMemorySize, K3_SMEM);
        attr_done = true;
    }

    k0_init<<<256, 256>>>(w);

    dim3 g2(P_ / 128, N_);
    k2_mma<<<g2, 128, K2_SMEM>>>(x);

    dim3 g3(D_ / 128, 2, N_);
    k3_mma<<<g3, 512, K3_SMEM>>>();

    dim3 g4(K_, N_);
    k4a_finalize<<<g4, 128>>>(c, out);

    k4b_global<<<(N_ * K_ * D_) / 256, 256>>>(out);
}

// round 17
// speedup vs baseline: 1.1509x; 1.1509x over previous
#include <cuda_runtime.h>
#include <cuda_bf16.h>
#include <math.h>
#include <stdint.h>

#define N_  32
#define D_  512
#define P_  4096
#define K_  64
#define EPSF 1e-12f

// ---------------- scratch (device globals) ----------------------------------
__device__ __nv_bfloat16 g_ah[(size_t)N_ * K_ * P_];    // a*invn bf16 (16 MB)
__device__ __nv_bfloat16 g_wh[K_ * D_];                 // W bf16 (64 KB)
__device__ float g_asum[N_ * K_];
__device__ float g_vlad[(size_t)N_ * K_ * D_];          // 4 MB

// ---------------- helpers ----------------------------------------------------
__device__ __forceinline__ uint32_t smem_u32(const void* p) {
    uint32_t a;
    asm("{ .reg .u64 t; cvta.to.shared.u64 t, %1; cvt.u32.u64 %0, t; }" : "=r"(a) : "l"(p));
    return a;
}
__device__ __forceinline__ void mma_bf16(float* c, const uint32_t* a, const uint32_t* b) {
    asm volatile(
        "mma.sync.aligned.m16n8k16.row.col.f32.bf16.bf16.f32 "
        "{%0,%1,%2,%3}, {%4,%5,%6,%7}, {%8,%9}, {%0,%1,%2,%3};"
        : "+f"(c[0]), "+f"(c[1]), "+f"(c[2]), "+f"(c[3])
        : "r"(a[0]), "r"(a[1]), "r"(a[2]), "r"(a[3]), "r"(b[0]), "r"(b[1]));
}
__device__ __forceinline__ void ldsm4(uint32_t* r, const void* p) {
    uint32_t a = smem_u32(p);
    asm volatile("ldmatrix.sync.aligned.m8n8.x4.shared.b16 {%0,%1,%2,%3}, [%4];"
        : "=r"(r[0]), "=r"(r[1]), "=r"(r[2]), "=r"(r[3]) : "r"(a));
}
__device__ __forceinline__ uint32_t pack2(float a, float b) {
    __nv_bfloat162 h = __floats2bfloat162_rn(a, b);
    return *(uint32_t*)&h;
}
__device__ __forceinline__ void pack4h(float4 v, uint2& h) {
    h.x = pack2(v.x, v.y);  h.y = pack2(v.z, v.w);
}
__device__ __forceinline__ void cp16(void* dst_smem, const void* src) {
    asm volatile("cp.async.cg.shared.global [%0], [%1], 16;"
                 :: "r"(smem_u32(dst_smem)), "l"(src) : "memory");
}
#define CP_COMMIT() asm volatile("cp.async.commit_group;" ::: "memory")
#define CP_WAIT0()  asm volatile("cp.async.wait_group 0;" ::: "memory")

// ---------------- k0: zero scratch + convert W to bf16 ------------------------
__global__ void k0_init(const float* __restrict__ wgt) {
    int i = blockIdx.x * 256 + threadIdx.x;
    if (i < N_ * K_) g_asum[i] = 0.f;
    if (i < K_ * D_) g_wh[i] = __float2bfloat16_rn(wgt[i]);
    for (int e = i; e < N_ * K_ * D_; e += gridDim.x * 256) g_vlad[e] = 0.f;
}

// ---------------- k2: fused norm + logits GEMM + softmax + a_eff + asum ------
// block = (n, 128 pixels), 128 threads (4 warps). R14 winner, unchanged.
#define ST2 40
#define WPART (64 * ST2)
#define TPART (128 * ST2)
#define BUF2_B ((WPART + TPART) * 2)            // 15360 bytes per buffer
#define LS_B (64 * 132 * 4)                     // 33792
#define K2_SMEM (LS_B + 512)                    // Ls unioned over both buffers

__global__ __launch_bounds__(128) void k2_mma(const float* __restrict__ x) {
    extern __shared__ char sm2[];
    float* Ls = (float*)sm2;                    // [64][132] — UNION with staging
    float* sInv = (float*)(sm2 + LS_B);         // [128]

    const int n  = blockIdx.y;
    const int p0 = blockIdx.x * 128;
    const int tid = threadIdx.x;
    const int w = tid >> 5, lane = tid & 31;
    const int g = lane >> 2, tc = lane & 3;

    const int a_row = (lane & 15);
    const int a_col = (lane >> 4) << 3;
    const int b_row = ((lane >> 4) << 3) + (lane & 7);
    const int b_col = ((lane >> 3) & 1) << 3;

    float acc[4][4][4];
    #pragma unroll
    for (int i = 0; i < 4; i++)
        #pragma unroll
        for (int j = 0; j < 4; j++)
            #pragma unroll
            for (int q = 0; q < 4; q++) acc[i][j][q] = 0.f;

    const float* xb = x + (size_t)n * D_ * P_ + p0 + tid;
    float ss = 0.f;

    const int wrow = tid >> 1;
    const int wseg = (tid & 1) * 16;

    float xr[32];

    // ---- prologue: stage chunk 0 into buffer 0 ----
    {
        char* buf = sm2;
        __nv_bfloat16* Wh = (__nv_bfloat16*)buf;
        __nv_bfloat16* Th = Wh + WPART;
        cp16(Wh + wrow * ST2 + wseg,     g_wh + wrow * D_ + wseg);
        cp16(Wh + wrow * ST2 + wseg + 8, g_wh + wrow * D_ + wseg + 8);
        CP_COMMIT();
        #pragma unroll
        for (int dd = 0; dd < 32; dd++) xr[dd] = xb[(size_t)dd * P_];
        #pragma unroll
        for (int dd = 0; dd < 32; dd += 4) {
            float4 v = {xr[dd], xr[dd + 1], xr[dd + 2], xr[dd + 3]};
            ss += v.x * v.x + v.y * v.y + v.z * v.z + v.w * v.w;
            uint2 h; pack4h(v, h);
            *(uint2*)(Th + tid * ST2 + dd) = h;
        }
        CP_WAIT0();
        __syncthreads();
    }

    for (int dc = 0; dc < 16; dc++) {
        const int b = dc & 1;
        char* buf = sm2 + b * BUF2_B;
        const __nv_bfloat16* Wh = (const __nv_bfloat16*)buf;
        const __nv_bfloat16* Th = Wh + WPART;

        char* nbuf = sm2 + (b ^ 1) * BUF2_B;
        __nv_bfloat16* nWh = (__nv_bfloat16*)nbuf;
        __nv_bfloat16* nTh = nWh + WPART;

        const bool more = (dc + 1 < 16);
        if (more) {
            const int nd0 = (dc + 1) * 32;
            cp16(nWh + wrow * ST2 + wseg,     g_wh + wrow * D_ + nd0 + wseg);
            cp16(nWh + wrow * ST2 + wseg + 8, g_wh + wrow * D_ + nd0 + wseg + 8);
            CP_COMMIT();
            #pragma unroll
            for (int dd = 0; dd < 32; dd++) xr[dd] = xb[(size_t)(nd0 + dd) * P_];
        }

        // ---- MMA on current buffer (single bf16 pass, ldmatrix feeds) ----
        const __nv_bfloat16* Arow = Wh + a_row * ST2 + a_col;
        const __nv_bfloat16* B01  = Th + (w * 32 + b_row) * ST2 + b_col;
        const __nv_bfloat16* B23  = B01 + 16 * ST2;
        #pragma unroll
        for (int ks = 0; ks < 2; ks++) {
            const int kb = ks * 16;
            uint32_t Bt[8];
            ldsm4(Bt,     B01 + kb);
            ldsm4(Bt + 4, B23 + kb);
            #pragma unroll
            for (int mt = 0; mt < 4; mt++) {
                uint32_t Ah[4];
                ldsm4(Ah, Arow + mt * 16 * ST2 + kb);
                #pragma unroll
                for (int t = 0; t < 4; t++)
                    mma_bf16(acc[mt][t], Ah, Bt + t * 2);
            }
        }

        if (more) {
            #pragma unroll
            for (int dd = 0; dd < 32; dd += 4) {
                float4 v = {xr[dd], xr[dd + 1], xr[dd + 2], xr[dd + 3]};
                ss += v.x * v.x + v.y * v.y + v.z * v.z + v.w * v.w;
                uint2 h; pack4h(v, h);
                *(uint2*)(nTh + tid * ST2 + dd) = h;
            }
            CP_WAIT0();
        }
        __syncthreads();
    }

    const float invnv = 1.0f / fmaxf(sqrtf(ss), EPSF);
    sInv[tid] = invnv;
    __syncthreads();

    // epilogue: scale by invn, stage logits into Ls (staging buffers dead now)
    #pragma unroll
    for (int mt = 0; mt < 4; mt++)
        #pragma unroll
        for (int t = 0; t < 4; t++) {
            int col = w * 32 + t * 8 + tc * 2;
            int row = mt * 16 + g;
            Ls[row * 132 + col]           = acc[mt][t][0] * sInv[col];
            Ls[row * 132 + col + 1]       = acc[mt][t][1] * sInv[col + 1];
            Ls[(row + 8) * 132 + col]     = acc[mt][t][2] * sInv[col];
            Ls[(row + 8) * 132 + col + 1] = acc[mt][t][3] * sInv[col + 1];
        }
    __syncthreads();

    // softmax over clusters; one thread per pixel column
    {
        float m = -1e30f;
        for (int k = 0; k < 64; k++) m = fmaxf(m, Ls[k * 132 + tid]);
        float s = 0.f;
        for (int k = 0; k < 64; k++) {
            float e = expf(Ls[k * 132 + tid] - m);
            Ls[k * 132 + tid] = e;
            s += e;
        }
        float inv = 1.0f / s;
        for (int k = 0; k < 64; k++) Ls[k * 132 + tid] *= inv;
    }
    __syncthreads();

    // write a_eff = a * invn as bf16
    {
        __nv_bfloat16* ah = g_ah + (size_t)n * K_ * P_ + p0 + tid;
        for (int k = 0; k < 64; k++) {
            float ae = Ls[k * 132 + tid] * invnv;
            ah[(size_t)k * P_] = __float2bfloat16_rn(ae);
        }
    }
    if (tid < 64) {
        float s = 0.f;
        for (int p = 0; p < 128; p++) s += Ls[tid * 132 + p];
        atomicAdd(&g_asum[n * K_ + tid], s);
    }
}

// ---------------- k3: vlad GEMM, single-pass bf16, p-split=2 (R14 winner) ----
#define PC3 64
#define ST3 72
#define XPART (128 * ST3)
#define APART (64 * ST3)
#define BUF_B ((XPART + APART) * 2)           // 27648 bytes per buffer
#define K3_SMEM (2 * BUF_B)                    // 55296 bytes
#define NCH3 (2048 / PC3)                      // 32 chunks per half

__global__ __launch_bounds__(512, 2) void k3_mma(const float* __restrict__ x) {
    extern __shared__ char sm3[];

    const int n    = blockIdx.z;
    const int d0   = blockIdx.x * 128;
    const int pho  = blockIdx.y * 2048;
    const int tid  = threadIdx.x;
    const int w = tid >> 5, lane = tid & 31;
    const int g = lane >> 2, tc = lane & 3;
    const int mt = w >> 1;
    const int nh = (w & 1) * 32;

    const int a_rowoff = (mt * 16 + (lane & 15)) * ST3 + ((lane >> 4) << 3);
    const int b_rowoff = (nh + ((lane >> 4) << 3) + (lane & 7)) * ST3 + (((lane >> 3) & 1) << 3);

    const float* xn = x + (size_t)n * D_ * P_ + (size_t)d0 * P_ + pho;
    const __nv_bfloat16* gah = g_ah + (size_t)n * K_ * P_ + pho;

    float acc[4][4];
    #pragma unroll
    for (int t = 0; t < 4; t++)
        #pragma unroll
        for (int q = 0; q < 4; q++) acc[t][q] = 0.f;

    const int c4 = tid & 15;
    const int r0 = tid >> 4;
    const int arow = tid >> 3;
    const int aseg = tid & 7;

    float4 xv[4];

    {   // prologue
        char* buf = sm3;
        __nv_bfloat16* Xh = (__nv_bfloat16*)buf;
        __nv_bfloat16* Ahs = Xh + XPART;
        cp16(Ahs + arow * ST3 + aseg * 8, gah + (size_t)arow * P_ + aseg * 8);
        CP_COMMIT();
        #pragma unroll
        for (int rr = 0; rr < 4; rr++)
            xv[rr] = *(const float4*)(xn + (size_t)(r0 + rr * 32) * P_ + c4 * 4);
        #pragma unroll
        for (int rr = 0; rr < 4; rr++) {
            int row = r0 + rr * 32;
            uint2 h; pack4h(xv[rr], h);
            *(uint2*)(Xh + row * ST3 + c4 * 4) = h;
        }
        CP_WAIT0();
        __syncthreads();
    }

    for (int pc = 0; pc < NCH3; pc++) {
        const int b = pc & 1;
        char* buf = sm3 + b * BUF_B;
        const __nv_bfloat16* Xh = (const __nv_bfloat16*)buf;
        const __nv_bfloat16* Ahs = Xh + XPART;

        char* nbuf = sm3 + (b ^ 1) * BUF_B;
        __nv_bfloat16* nXh = (__nv_bfloat16*)nbuf;
        __nv_bfloat16* nAh = nXh + XPART;

        const bool more = (pc + 1 < NCH3);
        if (more) {
            const int pb = (pc + 1) * PC3;
            cp16(nAh + arow * ST3 + aseg * 8, gah + (size_t)arow * P_ + pb + aseg * 8);
            CP_COMMIT();
            #pragma unroll
            for (int rr = 0; rr < 4; rr++)
                xv[rr] = *(const float4*)(xn + (size_t)(r0 + rr * 32) * P_ + pb + c4 * 4);
        }

        // ---- MMA on current buffer (single pass) ----
        #pragma unroll
        for (int ks = 0; ks < 4; ks++) {
            const int kb = ks * 16;
            uint32_t Bh[8];
            ldsm4(Bh,     Ahs + b_rowoff + kb);
            ldsm4(Bh + 4, Ahs + b_rowoff + 16 * ST3 + kb);
            uint32_t Ah[4];
            ldsm4(Ah, Xh + a_rowoff + kb);
            #pragma unroll
            for (int t = 0; t < 4; t++)
                mma_bf16(acc[t], Ah, Bh + t * 2);
        }

        if (more) {
            #pragma unroll
            for (int rr = 0; rr < 4; rr++) {
                int row = r0 + rr * 32;
                uint2 h; pack4h(xv[rr], h);
                *(uint2*)(nXh + row * ST3 + c4 * 4) = h;
            }
            CP_WAIT0();
        }
        __syncthreads();
    }

    float* vb = g_vlad + (size_t)n * K_ * D_ + d0;
    const int r = mt * 16 + g;
    #pragma unroll
    for (int t = 0; t < 4; t++) {
        int kc = nh + t * 8 + tc * 2;
        atomicAdd(&vb[(size_t)kc * D_ + r],           acc[t][0]);
        atomicAdd(&vb[(size_t)(kc + 1) * D_ + r],     acc[t][1]);
        atomicAdd(&vb[(size_t)kc * D_ + r + 8],       acc[t][2]);
        atomicAdd(&vb[(size_t)(kc + 1) * D_ + r + 8], acc[t][3]);
    }
}

// ---------------- k4a: centroid subtraction + intra-norm + global 1/8 --------
// Global norm after intra-normalization is exactly sqrt(K_) = 8 (each of the
// 64 cluster vectors is unit norm), so fold 0.125 into the store; k4b removed.
__global__ __launch_bounds__(128) void k4a_finalize(
        const float* __restrict__ cent, float* __restrict__ out) {
    const int k = blockIdx.x, n = blockIdx.y;
    const int tid = threadIdx.x;
    const float asum = g_asum[n * K_ + k];
    const float* vl = g_vlad + ((size_t)n * K_ + k) * D_;
    const float* ck = cent + (size_t)k * D_;

    float t[4];
    float s2 = 0.f;
    #pragma unroll
    for (int r = 0; r < 4; r++) {
        int d = r * 128 + tid;
        t[r] = vl[d] - asum * ck[d];
        s2 += t[r] * t[r];
    }
    #pragma unroll
    for (int o = 16; o > 0; o >>= 1) s2 += __shfl_xor_sync(0xffffffffu, s2, o);
    __shared__ float red[4];
    if ((tid & 31) == 0) red[tid >> 5] = s2;
    __syncthreads();
    float total = red[0] + red[1] + red[2] + red[3];
    float inv = 0.125f / fmaxf(sqrtf(total), EPSF);   // intra-norm x global 1/8

    float* o = out + ((size_t)n * K_ + k) * D_;
    #pragma unroll
    for (int r = 0; r < 4; r++) o[r * 128 + tid] = t[r] * inv;
}

// ---------------- launch --------------------------------------------------------
extern "C" void kernel_launch(void* const* d_in, const int* in_sizes, int n_in,
                              void* d_out, int out_size) {
    const float* x = (const float*)d_in[0];
    const float* w = (const float*)d_in[1];
    const float* c = (const float*)d_in[2];
    float* out = (float*)d_out;

    static bool attr_done = false;
    if (!attr_done) {
        cudaFuncSetAttribute(k2_mma, cudaFuncAttributeMaxDynamicSharedMemorySize, K2_SMEM);
        cudaFuncSetAttribute(k3_mma, cudaFuncAttributeMaxDynamicSharedMemorySize, K3_SMEM);
        attr_done = true;
    }

    k0_init<<<256, 256>>>(w);

    dim3 g2(P_ / 128, N_);
    k2_mma<<<g2, 128, K2_SMEM>>>(x);

    dim3 g3(D_ / 128, 2, N_);
    k3_mma<<<g3, 512, K3_SMEM>>>(x);

    dim3 g4(K_, N_);
    k4a_finalize<<<g4, 128>>>(c, out);
}